// round 14
// baseline (speedup 1.0000x reference)
#include <cuda_runtime.h>
#include <cuda_fp16.h>
#include <cstdint>
#include <math.h>

// Problem constants
constexpr int B_  = 8;
constexpr int C_  = 256;
constexpr int H_  = 31;
constexpr int W_  = 31;
constexpr int T_  = 7;
constexpr int K_  = 49;      // T*T
constexpr int OC_ = 147;     // 3*K
constexpr int OH_ = 25;
constexpr int OW_ = 25;
constexpr int HW_ = H_ * W_; // 961
constexpr int OHW_= OH_ * OW_; // 625

// GEMM view of the conv
constexpr int NPAD_ = 160;           // padded oc
constexpr int KTOT_ = C_ * 9;        // 2304
constexpr int KCH_  = 16 * 9;        // 144 k per 16-channel chunk

// Scratch (device globals; no allocations allowed)
__device__ __half g_srH[B_ * HW_ * C_];        // (B,H,W,C) fp16 (deform)
__device__ __half g_tmplH[B_ * K_ * C_];       // (B,K,C) fp16 (deform)
__device__ __half g_whk[NPAD_ * KTOT_];        // weights [n][k] fp16 (conv B)
__device__ float  g_om[B_ * OHW_ * NPAD_];     // conv out [b][pos][n] fp32

__device__ __forceinline__ __half2 u2h(unsigned int u) {
    return *reinterpret_cast<const __half2*>(&u);
}
__device__ __forceinline__ unsigned int packh(__half lo, __half hi) {
    __half2 h = __halves2half2(lo, hi);
    return *reinterpret_cast<unsigned int*>(&h);
}

// ---------------------------------------------------------------------------
// Fused prep: transpose sr (->fp16), transpose tmpl (->fp16), weights fp16.
// ---------------------------------------------------------------------------
constexpr int PREP_SR_BLKS   = 31 * 8 * 8;                    // 1984
constexpr int PREP_TMPL_BLKS = (B_ * K_ * C_ + 255) / 256;    // 392
constexpr int PREP_W_BLKS    = (NPAD_ * KTOT_ + 255) / 256;   // 1440
constexpr int PREP_BLKS = PREP_SR_BLKS + PREP_TMPL_BLKS + PREP_W_BLKS;

__global__ void __launch_bounds__(256) prep_kernel(
    const float* __restrict__ sr,
    const float* __restrict__ tmpl,
    const float* __restrict__ w)
{
    __shared__ float tile[32][33];
    const int bid = blockIdx.x;
    const int tid = threadIdx.x;

    if (bid < PREP_SR_BLKS) {
        int px = bid % 31;
        int cy = (bid / 31) % 8;
        int b  = bid / (31 * 8);
        int p0 = px * 32, c0 = cy * 32;
        int tx = tid % 32, ty = tid / 32;
        #pragma unroll
        for (int yy = 0; yy < 32; yy += 8) {
            int c = c0 + ty + yy, p = p0 + tx;
            if (p < HW_) tile[ty + yy][tx] = sr[(b * C_ + c) * HW_ + p];
        }
        __syncthreads();
        #pragma unroll
        for (int yy = 0; yy < 32; yy += 8) {
            int p = p0 + ty + yy, c = c0 + tx;
            if (p < HW_) g_srH[(b * HW_ + p) * C_ + c] = __float2half(tile[tx][ty + yy]);
        }
    } else if (bid < PREP_SR_BLKS + PREP_TMPL_BLKS) {
        int t = (bid - PREP_SR_BLKS) * 256 + tid;
        if (t < B_ * K_ * C_) {
            int c = t % C_;
            int k = (t / C_) % K_;
            int b = t / (C_ * K_);
            g_tmplH[t] = __float2half(tmpl[(b * C_ + c) * K_ + k]);
        }
    } else {
        int t = (bid - PREP_SR_BLKS - PREP_TMPL_BLKS) * 256 + tid;
        if (t < NPAD_ * KTOT_) {
            int n = t / KTOT_;
            int k = t % KTOT_;
            float v = (n < OC_) ? w[n * KTOT_ + k] : 0.0f;  // w is (147,256,3,3) = [n][k]
            g_whk[t] = __float2half(v);
        }
    }
}

// ---------------------------------------------------------------------------
// K2: conv as implicit GEMM with mma.sync m16n8k16 (fp16 in, fp32 accum).
// grid = (20, 8) = 160 blocks; block = 256 = 8 warps = 2(M) x 4(N).
// Block: 32 consecutive positions of one batch x all 160 (padded) oc.
// Per 16-channel chunk: stage weights [160][144] + sr rows [16][5][33] fp16.
// A fragments gathered from sr smem via (c,tap)->(dy,dx) indexing.
// Epilogue: g_om[b][pos][n] = D + bias.
// ---------------------------------------------------------------------------
__global__ void __launch_bounds__(256, 2) conv_mma_kernel(
    const float* __restrict__ sr,
    const float* __restrict__ bias)
{
    extern __shared__ char dsm[];
    __half* s_B  = (__half*)dsm;                          // [160][144]
    char*   s_sr = dsm + NPAD_ * KCH_ * 2;                // [16][5][33] halfs

    const int bm  = blockIdx.x;   // 0..19 (M tile within batch)
    const int b   = blockIdx.y;
    const int tid = threadIdx.x;
    const int wid = tid / 32, lane = tid % 32;
    const int g   = lane / 4;
    const int t2  = (lane % 4) * 2;
    const int warpM = wid % 2;
    const int warpN = wid / 2;

    const int p0     = bm * 32;
    const int i_base = p0 / OW_;

    const int pos0 = p0 + warpM * 16 + g;
    const int pos1 = pos0 + 8;
    const int i0 = pos0 / OW_, j0 = pos0 % OW_;
    const int i1 = pos1 / OW_, j1 = pos1 % OW_;
    // base byte offsets into s_sr for this thread's two rows
    const int abase0 = ((i0 - i_base) * 33 + j0) * 2;
    const int abase1 = ((i1 - i_base) * 33 + j1) * 2;

    float acc[5][4];
    #pragma unroll
    for (int t = 0; t < 5; t++)
        #pragma unroll
        for (int q = 0; q < 4; q++) acc[t][q] = 0.0f;

    for (int cc = 0; cc < 16; cc++) {
        __syncthreads();
        // stage weights chunk: s_B[n][0..143] <- g_whk[n][cc*144 ..]
        for (int e = tid; e < (NPAD_ * KCH_) / 8; e += 256) {
            int n = e / 18, col = e % 18;
            *(((float4*)s_B) + e) =
                *(const float4*)((const char*)g_whk + ((size_t)n * KTOT_ + cc * KCH_) * 2 + col * 16);
        }
        // stage sr rows: 16 ch x rows i_base-1..i_base+3 x cols -1..31 (fp16)
        for (int e = tid; e < 16 * 5 * 33; e += 256) {
            int c = e / 165, rem = e % 165, r = rem / 33, xp = rem % 33;
            int gy = i_base - 1 + r;
            int gx = xp - 1;
            float v = 0.f;
            if (gy >= 0 && gy < H_ && gx >= 0 && gx < W_)
                v = sr[((b * C_ + cc * 16 + c) * H_ + gy) * W_ + gx];
            ((__half*)s_sr)[e] = __float2half(v);
        }
        __syncthreads();

        #pragma unroll
        for (int kk = 0; kk < 9; kk++) {
            const int k0 = kk * 16 + t2;   // A cols k0, k0+1
            const int k8 = k0 + 8;         // A cols k8, k8+1

            // byte offsets within s_sr for the 4 k values
            int c0i = k0 / 9, tp0 = k0 % 9;
            int c1i = (k0 + 1) / 9, tp1 = (k0 + 1) % 9;
            int c8i = k8 / 9, tp8 = k8 % 9;
            int c9i = (k8 + 1) / 9, tp9 = (k8 + 1) % 9;
            int o0 = c0i * 330 + (tp0 / 3) * 66 + (tp0 % 3) * 2;
            int o1 = c1i * 330 + (tp1 / 3) * 66 + (tp1 % 3) * 2;
            int o8 = c8i * 330 + (tp8 / 3) * 66 + (tp8 % 3) * 2;
            int o9 = c9i * 330 + (tp9 / 3) * 66 + (tp9 % 3) * 2;

            unsigned int a0 = packh(*(const __half*)(s_sr + abase0 + o0),
                                    *(const __half*)(s_sr + abase0 + o1));
            unsigned int a1 = packh(*(const __half*)(s_sr + abase1 + o0),
                                    *(const __half*)(s_sr + abase1 + o1));
            unsigned int a2 = packh(*(const __half*)(s_sr + abase0 + o8),
                                    *(const __half*)(s_sr + abase0 + o9));
            unsigned int a3 = packh(*(const __half*)(s_sr + abase1 + o8),
                                    *(const __half*)(s_sr + abase1 + o9));

            #pragma unroll
            for (int t = 0; t < 5; t++) {
                int n = warpN * 40 + t * 8 + g;
                const char* bb = (const char*)s_B + n * (KCH_ * 2) + k0 * 2;
                unsigned int b0 = *(const unsigned int*)(bb);
                unsigned int b1 = *(const unsigned int*)(bb + 16);
                asm volatile(
                    "mma.sync.aligned.m16n8k16.row.col.f32.f16.f16.f32 "
                    "{%0,%1,%2,%3}, {%4,%5,%6,%7}, {%8,%9}, {%0,%1,%2,%3};"
                    : "+f"(acc[t][0]), "+f"(acc[t][1]), "+f"(acc[t][2]), "+f"(acc[t][3])
                    : "r"(a0), "r"(a1), "r"(a2), "r"(a3), "r"(b0), "r"(b1));
            }
        }
    }

    // epilogue: D + bias -> g_om[b][pos][n]
    #pragma unroll
    for (int t = 0; t < 5; t++) {
        int n = warpN * 40 + t * 8 + t2;
        float bv0 = (n     < OC_) ? bias[n]     : 0.0f;
        float bv1 = (n + 1 < OC_) ? bias[n + 1] : 0.0f;
        if (pos0 < OHW_) {
            float2 v = make_float2(acc[t][0] + bv0, acc[t][1] + bv1);
            *(float2*)(g_om + ((size_t)b * OHW_ + pos0) * NPAD_ + n) = v;
        }
        if (pos1 < OHW_) {
            float2 v = make_float2(acc[t][2] + bv0, acc[t][3] + bv1);
            *(float2*)(g_om + ((size_t)b * OHW_ + pos1) * NPAD_ + n) = v;
        }
    }
}

// ---------------------------------------------------------------------------
// K3: deformable bilinear gather + weighted correlation (validated R13 form,
// g_om reads updated to [b][pos][n] layout — coalesced metadata).
// block = 256 = 8 warps = 8 positions; lane = 8 channels (LDG.128 fp16).
// ---------------------------------------------------------------------------
__global__ void __launch_bounds__(256) deform_xcorr_kernel(float* __restrict__ out)
{
    __shared__ int4  sA4[8][K_];
    __shared__ uint4 sWh[8][K_];

    const int tid = threadIdx.x;

    for (int e = tid; e < 8 * K_; e += 256) {
        const int g2 = e / K_;
        const int k  = e % K_;
        const int p  = blockIdx.x * 8 + g2;
        const int b  = p / OHW_;
        const int rem = p % OHW_;
        const int i  = rem / OW_;
        const int j  = rem % OW_;

        const size_t base = ((size_t)b * OHW_ + rem) * NPAD_;
        float oy = g_om[base + k];
        float ox = g_om[base + k + 49];
        float mz = g_om[base + k + 98];
        float m  = 1.0f / (1.0f + __expf(-mz));

        float ys = (float)i + (float)(k / T_) + oy;
        float xs = (float)j + (float)(k % T_) + ox;
        float y0f = floorf(ys), x0f = floorf(xs);
        float wy = ys - y0f, wx = xs - x0f;
        float y1f = y0f + 1.0f, x1f = x0f + 1.0f;

        bool vy0 = (y0f >= 0.0f) && (y0f <= (float)(H_ - 1));
        bool vy1 = (y1f >= 0.0f) && (y1f <= (float)(H_ - 1));
        bool vx0 = (x0f >= 0.0f) && (x0f <= (float)(W_ - 1));
        bool vx1 = (x1f >= 0.0f) && (x1f <= (float)(W_ - 1));

        float w00 = (1.0f - wy) * (1.0f - wx) * m; if (!(vy0 && vx0)) w00 = 0.0f;
        float w01 = (1.0f - wy) * wx          * m; if (!(vy0 && vx1)) w01 = 0.0f;
        float w10 = wy          * (1.0f - wx) * m; if (!(vy1 && vx0)) w10 = 0.0f;
        float w11 = wy          * wx          * m; if (!(vy1 && vx1)) w11 = 0.0f;

        int y0 = (int)fminf(fmaxf(y0f, 0.0f), (float)(H_ - 1));
        int y1 = (int)fminf(fmaxf(y1f, 0.0f), (float)(H_ - 1));
        int x0 = (int)fminf(fmaxf(x0f, 0.0f), (float)(W_ - 1));
        int x1 = (int)fminf(fmaxf(x1f, 0.0f), (float)(W_ - 1));

        sA4[g2][k] = make_int4((y0 * W_ + x0) * (C_ * 2),
                               (y0 * W_ + x1) * (C_ * 2),
                               (y1 * W_ + x0) * (C_ * 2),
                               (y1 * W_ + x1) * (C_ * 2));
        __half2 h00 = __float2half2_rn(w00);
        __half2 h01 = __float2half2_rn(w01);
        __half2 h10 = __float2half2_rn(w10);
        __half2 h11 = __float2half2_rn(w11);
        sWh[g2][k] = make_uint4(*reinterpret_cast<unsigned int*>(&h00),
                                *reinterpret_cast<unsigned int*>(&h01),
                                *reinterpret_cast<unsigned int*>(&h10),
                                *reinterpret_cast<unsigned int*>(&h11));
    }
    __syncthreads();

    const int g  = tid / 32;
    const int l  = tid % 32;
    const int p  = blockIdx.x * 8 + g;
    const int b  = p / OHW_;
    const int rem = p % OHW_;
    const int i  = rem / OW_;
    const int j  = rem % OW_;

    const char* srHb = (const char*)g_srH + ((size_t)b * HW_ * C_) * 2 + l * 16;
    const char* tHb  = (const char*)g_tmplH + ((size_t)b * K_ * C_) * 2 + l * 16;

    float acc[8];
    #pragma unroll
    for (int q = 0; q < 8; q++) acc[q] = 0.0f;

    #pragma unroll 7
    for (int k = 0; k < K_; k++) {
        int4  a  = sA4[g][k];
        uint4 wh = sWh[g][k];
        __half2 w00 = u2h(wh.x), w01 = u2h(wh.y), w10 = u2h(wh.z), w11 = u2h(wh.w);

        uint4 u00 = *(const uint4*)(srHb + a.x);
        uint4 u01 = *(const uint4*)(srHb + a.y);
        uint4 u10 = *(const uint4*)(srHb + a.z);
        uint4 u11 = *(const uint4*)(srHb + a.w);
        uint4 ut  = *(const uint4*)(tHb + k * (C_ * 2));

        __half2 v0 = __hmul2(w00, u2h(u00.x));
        v0 = __hfma2(w01, u2h(u01.x), v0);
        v0 = __hfma2(w10, u2h(u10.x), v0);
        v0 = __hfma2(w11, u2h(u11.x), v0);
        __half2 v1 = __hmul2(w00, u2h(u00.y));
        v1 = __hfma2(w01, u2h(u01.y), v1);
        v1 = __hfma2(w10, u2h(u10.y), v1);
        v1 = __hfma2(w11, u2h(u11.y), v1);
        __half2 v2 = __hmul2(w00, u2h(u00.z));
        v2 = __hfma2(w01, u2h(u01.z), v2);
        v2 = __hfma2(w10, u2h(u10.z), v2);
        v2 = __hfma2(w11, u2h(u11.z), v2);
        __half2 v3 = __hmul2(w00, u2h(u00.w));
        v3 = __hfma2(w01, u2h(u01.w), v3);
        v3 = __hfma2(w10, u2h(u10.w), v3);
        v3 = __hfma2(w11, u2h(u11.w), v3);

        float2 f0 = __half22float2(v0);
        float2 f1 = __half22float2(v1);
        float2 f2 = __half22float2(v2);
        float2 f3 = __half22float2(v3);
        float2 t0 = __half22float2(u2h(ut.x));
        float2 t1 = __half22float2(u2h(ut.y));
        float2 t2 = __half22float2(u2h(ut.z));
        float2 t3 = __half22float2(u2h(ut.w));

        acc[0] = fmaf(t0.x, f0.x, acc[0]);
        acc[1] = fmaf(t0.y, f0.y, acc[1]);
        acc[2] = fmaf(t1.x, f1.x, acc[2]);
        acc[3] = fmaf(t1.y, f1.y, acc[3]);
        acc[4] = fmaf(t2.x, f2.x, acc[4]);
        acc[5] = fmaf(t2.y, f2.y, acc[5]);
        acc[6] = fmaf(t3.x, f3.x, acc[6]);
        acc[7] = fmaf(t3.y, f3.y, acc[7]);
    }

    const int c = l * 8;
    float* op = out + ((size_t)(b * C_ + c) * OH_ + i) * OW_ + j;
    #pragma unroll
    for (int q = 0; q < 8; q++)
        op[q * OHW_] = acc[q];
}

// ---------------------------------------------------------------------------
extern "C" void kernel_launch(void* const* d_in, const int* in_sizes, int n_in,
                              void* d_out, int out_size)
{
    const float* sr   = (const float*)d_in[0];
    const float* tmpl = (const float*)d_in[1];
    const float* w    = (const float*)d_in[2];
    const float* bias = (const float*)d_in[3];
    float* out = (float*)d_out;

    const int smem_conv = NPAD_ * KCH_ * 2 + 16 * 5 * 33 * 2;   // 51360 B
    cudaFuncSetAttribute(conv_mma_kernel,
                         cudaFuncAttributeMaxDynamicSharedMemorySize, smem_conv);

    prep_kernel<<<PREP_BLKS, 256>>>(sr, tmpl, w);
    {
        dim3 g(20, B_);
        conv_mma_kernel<<<g, 256, smem_conv>>>(sr, bias);
    }
    deform_xcorr_kernel<<<625, 256>>>(out);
}